// round 4
// baseline (speedup 1.0000x reference)
#include <cuda_runtime.h>

#define NP 200000
#define NA 100000
#define NI 8000
#define NF 30000
#define HD 256
#define NOUT 349
#define E_C 500000
#define E_W 400000
#define E_A 100000
#define E_T 300000

// ---------------- scratch (static device allocations, allowed) ----------------
__device__ float g_mp0[(size_t)NP * HD];   // mean cites -> p
__device__ float g_mp1[(size_t)NP * HD];   // mean writes -> p
__device__ float g_mp6[(size_t)NP * HD];   // mean rev_topic -> p
__device__ float g_ma2[(size_t)NA * HD];   // mean rev_writes -> a
__device__ float g_ma4[(size_t)NA * HD];   // mean rev_aff -> a
__device__ float g_mi3[(size_t)NI * HD];   // mean aff -> i
__device__ float g_mf5[(size_t)NF * HD];   // mean topic -> f

__device__ float g_pb[2][(size_t)NP * HD]; // ping-pong node features
__device__ float g_ab[2][(size_t)NA * HD];
__device__ float g_ib[2][(size_t)NI * HD];
__device__ float g_fb[2][(size_t)NF * HD];

__device__ float g_WrP[2 * HD * HD];       // combined Wr for paper (r0+r1+r6), per layer
__device__ float g_WrA[2 * HD * HD];       // combined Wr for author (r2+r4)
__device__ float g_bP[2 * HD];
__device__ float g_bA[2 * HD];

// CSR scratch: cnt doubles as cursor after scan
__device__ int g_cnt_c[NP];   __device__ int g_off_c[NP + 1];   __device__ int g_adj_c[E_C];
__device__ int g_cnt_w[NP];   __device__ int g_off_w[NP + 1];   __device__ int g_adj_w[E_W];
__device__ int g_cnt_rw[NA];  __device__ int g_off_rw[NA + 1];  __device__ int g_adj_rw[E_W];
__device__ int g_cnt_af[NI];  __device__ int g_off_af[NI + 1];  __device__ int g_adj_af[E_A];
__device__ int g_cnt_raf[NA]; __device__ int g_off_raf[NA + 1]; __device__ int g_adj_raf[E_A];
__device__ int g_cnt_t[NF];   __device__ int g_off_t[NF + 1];   __device__ int g_adj_t[E_T];
__device__ int g_cnt_rt[NP];  __device__ int g_off_rt[NP + 1];  __device__ int g_adj_rt[E_T];

// ---------------- kernels ----------------
__global__ void hist_kernel(const int* __restrict__ dst, int E, int* cnt) {
    int i = blockIdx.x * blockDim.x + threadIdx.x;
    if (i < E) atomicAdd(&cnt[dst[i]], 1);
}

// single-block exclusive scan; writes offs[0..n] and overwrites cnt with cursor=offs
__global__ void scan_kernel(int* cnt, int n, int* offs) {
    __shared__ int sh[1024];
    int tid = threadIdx.x;
    int chunk = (n + 1023) >> 10;
    int beg = tid * chunk;
    int end = beg + chunk; if (end > n) end = n;
    int s = 0;
    for (int i = beg; i < end; i++) s += cnt[i];
    sh[tid] = s;
    __syncthreads();
    for (int d = 1; d < 1024; d <<= 1) {
        int t = (tid >= d) ? sh[tid - d] : 0;
        __syncthreads();
        sh[tid] += t;
        __syncthreads();
    }
    int run = sh[tid] - s;  // exclusive base
    for (int i = beg; i < end; i++) {
        int c = cnt[i];
        offs[i] = run;
        cnt[i]  = run;   // cursor init
        run += c;
    }
    if (beg < n && end == n) offs[n] = run;
}

__global__ void fill_kernel(const int* __restrict__ src, const int* __restrict__ dst,
                            int E, int* cursor, int* __restrict__ adj) {
    int i = blockIdx.x * blockDim.x + threadIdx.x;
    if (i < E) {
        int p = atomicAdd(&cursor[dst[i]], 1);
        adj[p] = src[i];
    }
}

// mean aggregation: 64 threads per dst node (float4 per thread), 4 nodes per block
__global__ void gather_mean_kernel(const float* __restrict__ x,
                                   const int* __restrict__ offs,
                                   const int* __restrict__ adj,
                                   float* __restrict__ out, int n_dst) {
    int node = blockIdx.x * 4 + (threadIdx.x >> 6);
    int lane = threadIdx.x & 63;
    if (node >= n_dst) return;
    int beg = offs[node], end = offs[node + 1];
    float4 acc = make_float4(0.f, 0.f, 0.f, 0.f);
    int e = beg;
    for (; e + 1 < end; e += 2) {
        int s0 = adj[e], s1 = adj[e + 1];
        float4 v0 = ((const float4*)(x + (size_t)s0 * HD))[lane];
        float4 v1 = ((const float4*)(x + (size_t)s1 * HD))[lane];
        acc.x += v0.x + v1.x; acc.y += v0.y + v1.y;
        acc.z += v0.z + v1.z; acc.w += v0.w + v1.w;
    }
    if (e < end) {
        float4 v = ((const float4*)(x + (size_t)adj[e] * HD))[lane];
        acc.x += v.x; acc.y += v.y; acc.z += v.z; acc.w += v.w;
    }
    float inv = (end > beg) ? 1.f / (float)(end - beg) : 0.f;
    float4 r = make_float4(acc.x * inv, acc.y * inv, acc.z * inv, acc.w * inv);
    ((float4*)(out + (size_t)node * HD))[lane] = r;
}

// combine per-relation Wr/bias into per-nodetype sums (linearity of x_dst @ Wr terms)
__global__ void combine_kernel(const float* __restrict__ Wr, const float* __restrict__ bl,
                               float* __restrict__ WrP, float* __restrict__ WrA,
                               float* __restrict__ bP, float* __restrict__ bA) {
    int idx = blockIdx.x * blockDim.x + threadIdx.x;
    if (idx < 2 * HD * HD) {
        int l = idx / (HD * HD), j = idx % (HD * HD);
        const float* base = Wr + (size_t)l * 7 * HD * HD;
        WrP[idx] = base[0 * HD * HD + j] + base[1 * HD * HD + j] + base[6 * HD * HD + j];
        WrA[idx] = base[2 * HD * HD + j] + base[4 * HD * HD + j];
    }
    if (idx < 2 * HD) {
        int l = idx / HD, j = idx % HD;
        const float* bb = bl + (size_t)l * 7 * HD;
        bP[idx] = bb[0 * HD + j] + bb[1 * HD + j] + bb[6 * HD + j];
        bA[idx] = bb[2 * HD + j] + bb[4 * HD + j];
    }
}

// multi-part fused SGEMM: C[M,N] = act( sum_p A_p[M,256] @ W_p[256,N] + bias )
struct GemmArgs {
    const float* A[4];
    const float* W[4];
    int nparts, M, N;
    const float* bias;
    float* C;
    int relu;
};

__global__ __launch_bounds__(256) void gemm_kernel(GemmArgs g) {
    __shared__ float As[16][132];
    __shared__ float Bs[16][132];
    int tid = threadIdx.x;
    int bm = blockIdx.y * 128;
    int bn = blockIdx.x * 128;
    int ty = tid >> 4, tx = tid & 15;
    int ar = tid >> 2, ak = (tid & 3) * 4;   // A loader: rows ar, ar+64; cols ak..ak+3
    int br = tid >> 5, bc = (tid & 31) * 4;  // B loader: rows br, br+8; cols bc..bc+3

    float acc[8][8];
#pragma unroll
    for (int i = 0; i < 8; i++)
#pragma unroll
        for (int j = 0; j < 8; j++) acc[i][j] = 0.f;

    for (int p = 0; p < g.nparts; p++) {
        const float* A = g.A[p];
        const float* W = g.W[p];
        for (int k0 = 0; k0 < HD; k0 += 16) {
            // load A tile (transposed into As[k][m])
#pragma unroll
            for (int h = 0; h < 2; h++) {
                int row = bm + ar + h * 64;
                float4 v = make_float4(0.f, 0.f, 0.f, 0.f);
                if (row < g.M) v = *(const float4*)(A + (size_t)row * HD + k0 + ak);
                As[ak + 0][ar + h * 64] = v.x;
                As[ak + 1][ar + h * 64] = v.y;
                As[ak + 2][ar + h * 64] = v.z;
                As[ak + 3][ar + h * 64] = v.w;
            }
            // load B tile (scalar, guarded for N not multiple of 4/128)
#pragma unroll
            for (int h = 0; h < 2; h++) {
                int krow = k0 + br + h * 8;
#pragma unroll
                for (int j = 0; j < 4; j++) {
                    int col = bn + bc + j;
                    Bs[br + h * 8][bc + j] =
                        (col < g.N) ? W[(size_t)krow * g.N + col] : 0.f;
                }
            }
            __syncthreads();
#pragma unroll
            for (int k = 0; k < 16; k++) {
                float a[8], b[8];
#pragma unroll
                for (int i = 0; i < 8; i++) a[i] = As[k][ty * 8 + i];
#pragma unroll
                for (int j = 0; j < 8; j++) b[j] = Bs[k][tx * 8 + j];
#pragma unroll
                for (int i = 0; i < 8; i++)
#pragma unroll
                    for (int j = 0; j < 8; j++) acc[i][j] += a[i] * b[j];
            }
            __syncthreads();
        }
    }

#pragma unroll
    for (int i = 0; i < 8; i++) {
        int row = bm + ty * 8 + i;
        if (row >= g.M) continue;
#pragma unroll
        for (int j = 0; j < 8; j++) {
            int col = bn + tx * 8 + j;
            if (col >= g.N) continue;
            float v = acc[i][j];
            if (g.bias) v += g.bias[col];
            if (g.relu) v = v > 0.f ? v : 0.f;
            g.C[(size_t)row * g.N + col] = v;
        }
    }
}

// ---------------- host ----------------
static inline int cdiv(int a, int b) { return (a + b - 1) / b; }

static void launch_gemm(int M, int N, int nparts,
                        const float* A0, const float* W0,
                        const float* A1, const float* W1,
                        const float* A2, const float* W2,
                        const float* A3, const float* W3,
                        const float* bias, float* C, int relu) {
    GemmArgs g;
    g.A[0] = A0; g.A[1] = A1; g.A[2] = A2; g.A[3] = A3;
    g.W[0] = W0; g.W[1] = W1; g.W[2] = W2; g.W[3] = W3;
    g.nparts = nparts; g.M = M; g.N = N;
    g.bias = bias; g.C = C; g.relu = relu;
    dim3 grid(cdiv(N, 128), cdiv(M, 128));
    gemm_kernel<<<grid, 256>>>(g);
}

extern "C" void kernel_launch(void* const* d_in, const int* in_sizes, int n_in,
                              void* d_out, int out_size) {
    const float* xp = (const float*)d_in[0];
    const float* xa = (const float*)d_in[1];
    const float* xi = (const float*)d_in[2];
    const float* xf = (const float*)d_in[3];
    const int* cites_src = (const int*)d_in[4];
    const int* cites_dst = (const int*)d_in[5];
    const int* writes_src = (const int*)d_in[6];
    const int* writes_dst = (const int*)d_in[7];
    const int* rwrites_src = (const int*)d_in[8];
    const int* rwrites_dst = (const int*)d_in[9];
    const int* aff_src = (const int*)d_in[10];
    const int* aff_dst = (const int*)d_in[11];
    const int* raff_src = (const int*)d_in[12];
    const int* raff_dst = (const int*)d_in[13];
    const int* topic_src = (const int*)d_in[14];
    const int* topic_dst = (const int*)d_in[15];
    const int* rtopic_src = (const int*)d_in[16];
    const int* rtopic_dst = (const int*)d_in[17];
    const float* Wl = (const float*)d_in[18];
    const float* bl = (const float*)d_in[19];
    const float* Wr = (const float*)d_in[20];
    const float* Wout = (const float*)d_in[21];
    const float* bout = (const float*)d_in[22];

    // resolve scratch symbols (query only; not an allocation)
    float *mp0, *mp1, *mp6, *ma2, *ma4, *mi3, *mf5;
    float *pb, *ab, *ib, *fb, *WrP, *WrA, *bP, *bA;
    int *cnt_c, *off_c, *adj_c, *cnt_w, *off_w, *adj_w;
    int *cnt_rw, *off_rw, *adj_rw, *cnt_af, *off_af, *adj_af;
    int *cnt_raf, *off_raf, *adj_raf, *cnt_t, *off_t, *adj_t;
    int *cnt_rt, *off_rt, *adj_rt;
    cudaGetSymbolAddress((void**)&mp0, g_mp0);
    cudaGetSymbolAddress((void**)&mp1, g_mp1);
    cudaGetSymbolAddress((void**)&mp6, g_mp6);
    cudaGetSymbolAddress((void**)&ma2, g_ma2);
    cudaGetSymbolAddress((void**)&ma4, g_ma4);
    cudaGetSymbolAddress((void**)&mi3, g_mi3);
    cudaGetSymbolAddress((void**)&mf5, g_mf5);
    cudaGetSymbolAddress((void**)&pb, g_pb);
    cudaGetSymbolAddress((void**)&ab, g_ab);
    cudaGetSymbolAddress((void**)&ib, g_ib);
    cudaGetSymbolAddress((void**)&fb, g_fb);
    cudaGetSymbolAddress((void**)&WrP, g_WrP);
    cudaGetSymbolAddress((void**)&WrA, g_WrA);
    cudaGetSymbolAddress((void**)&bP, g_bP);
    cudaGetSymbolAddress((void**)&bA, g_bA);
    cudaGetSymbolAddress((void**)&cnt_c, g_cnt_c);
    cudaGetSymbolAddress((void**)&off_c, g_off_c);
    cudaGetSymbolAddress((void**)&adj_c, g_adj_c);
    cudaGetSymbolAddress((void**)&cnt_w, g_cnt_w);
    cudaGetSymbolAddress((void**)&off_w, g_off_w);
    cudaGetSymbolAddress((void**)&adj_w, g_adj_w);
    cudaGetSymbolAddress((void**)&cnt_rw, g_cnt_rw);
    cudaGetSymbolAddress((void**)&off_rw, g_off_rw);
    cudaGetSymbolAddress((void**)&adj_rw, g_adj_rw);
    cudaGetSymbolAddress((void**)&cnt_af, g_cnt_af);
    cudaGetSymbolAddress((void**)&off_af, g_off_af);
    cudaGetSymbolAddress((void**)&adj_af, g_adj_af);
    cudaGetSymbolAddress((void**)&cnt_raf, g_cnt_raf);
    cudaGetSymbolAddress((void**)&off_raf, g_off_raf);
    cudaGetSymbolAddress((void**)&adj_raf, g_adj_raf);
    cudaGetSymbolAddress((void**)&cnt_t, g_cnt_t);
    cudaGetSymbolAddress((void**)&off_t, g_off_t);
    cudaGetSymbolAddress((void**)&adj_t, g_adj_t);
    cudaGetSymbolAddress((void**)&cnt_rt, g_cnt_rt);
    cudaGetSymbolAddress((void**)&off_rt, g_off_rt);
    cudaGetSymbolAddress((void**)&adj_rt, g_adj_rt);

    float* pbuf[2] = { pb, pb + (size_t)NP * HD };
    float* abuf[2] = { ab, ab + (size_t)NA * HD };
    float* ibuf[2] = { ib, ib + (size_t)NI * HD };
    float* fbuf[2] = { fb, fb + (size_t)NF * HD };

    // ---- build CSR for all 7 relations (reused by both layers) ----
    struct Rel { const int* src; const int* dst; int E; int n_dst; int* cnt; int* off; int* adj; };
    Rel rels[7] = {
        { cites_src,   cites_dst,   E_C, NP, cnt_c,   off_c,   adj_c   },
        { writes_src,  writes_dst,  E_W, NP, cnt_w,   off_w,   adj_w   },
        { rwrites_src, rwrites_dst, E_W, NA, cnt_rw,  off_rw,  adj_rw  },
        { aff_src,     aff_dst,     E_A, NI, cnt_af,  off_af,  adj_af  },
        { raff_src,    raff_dst,    E_A, NA, cnt_raf, off_raf, adj_raf },
        { topic_src,   topic_dst,   E_T, NF, cnt_t,   off_t,   adj_t   },
        { rtopic_src,  rtopic_dst,  E_T, NP, cnt_rt,  off_rt,  adj_rt  },
    };
    for (int r = 0; r < 7; r++) {
        cudaMemsetAsync(rels[r].cnt, 0, (size_t)rels[r].n_dst * sizeof(int), 0);
        hist_kernel<<<cdiv(rels[r].E, 256), 256>>>(rels[r].dst, rels[r].E, rels[r].cnt);
        scan_kernel<<<1, 1024>>>(rels[r].cnt, rels[r].n_dst, rels[r].off);
        fill_kernel<<<cdiv(rels[r].E, 256), 256>>>(rels[r].src, rels[r].dst, rels[r].E,
                                                   rels[r].cnt, rels[r].adj);
    }

    // ---- combine Wr / biases per node type (both layers) ----
    combine_kernel<<<cdiv(2 * HD * HD, 256), 256>>>(Wr, bl, WrP, WrA, bP, bA);

    // ---- 2 SAGE layers ----
    const float* cp = xp; const float* ca = xa; const float* ci = xi; const float* cf = xf;
    for (int l = 0; l < 2; l++) {
        gather_mean_kernel<<<cdiv(NP, 4), 256>>>(cp, off_c,   adj_c,   mp0, NP);
        gather_mean_kernel<<<cdiv(NP, 4), 256>>>(ca, off_w,   adj_w,   mp1, NP);
        gather_mean_kernel<<<cdiv(NP, 4), 256>>>(cf, off_rt,  adj_rt,  mp6, NP);
        gather_mean_kernel<<<cdiv(NA, 4), 256>>>(cp, off_rw,  adj_rw,  ma2, NA);
        gather_mean_kernel<<<cdiv(NA, 4), 256>>>(ci, off_raf, adj_raf, ma4, NA);
        gather_mean_kernel<<<cdiv(NI, 4), 256>>>(ca, off_af,  adj_af,  mi3, NI);
        gather_mean_kernel<<<cdiv(NF, 4), 256>>>(cp, off_t,   adj_t,   mf5, NF);

        const size_t WSZ = (size_t)HD * HD;
        const float* WlL = Wl + (size_t)l * 7 * WSZ;
        const float* blL = bl + (size_t)l * 7 * HD;

        // new_p = relu(mp0@Wl0 + mp1@Wl1 + mp6@Wl6 + p@(Wr0+Wr1+Wr6) + (bl0+bl1+bl6))
        launch_gemm(NP, HD, 4,
                    mp0, WlL + 0 * WSZ, mp1, WlL + 1 * WSZ,
                    mp6, WlL + 6 * WSZ, cp, WrP + (size_t)l * WSZ,
                    bP + (size_t)l * HD, pbuf[l], 1);
        // new_a
        launch_gemm(NA, HD, 3,
                    ma2, WlL + 2 * WSZ, ma4, WlL + 4 * WSZ,
                    ca, WrA + (size_t)l * WSZ, 0, 0,
                    bA + (size_t)l * HD, abuf[l], 1);
        // new_i
        launch_gemm(NI, HD, 2,
                    mi3, WlL + 3 * WSZ, ci, Wr + ((size_t)l * 7 + 3) * WSZ,
                    0, 0, 0, 0,
                    blL + 3 * HD, ibuf[l], 1);
        // new_f
        launch_gemm(NF, HD, 2,
                    mf5, WlL + 5 * WSZ, cf, Wr + ((size_t)l * 7 + 5) * WSZ,
                    0, 0, 0, 0,
                    blL + 5 * HD, fbuf[l], 1);

        cp = pbuf[l]; ca = abuf[l]; ci = ibuf[l]; cf = fbuf[l];
    }

    // ---- final projection: out = p @ W_out + b_out ----
    launch_gemm(NP, NOUT, 1, cp, Wout, 0, 0, 0, 0, 0, 0,
                bout, (float*)d_out, 0);
}

// round 9
// speedup vs baseline: 1.7470x; 1.7470x over previous
#include <cuda_runtime.h>
#include <cstdint>

#define NP 200000
#define NA 100000
#define NI 8000
#define NF 30000
#define HD 256
#define NOUT 349
#define E_C 500000
#define E_W 400000
#define E_A 100000
#define E_T 300000

// ---------------- scratch (static device allocations, allowed) ----------------
__device__ float g_mp0[(size_t)NP * HD];   // mean cites -> p
__device__ float g_mp1[(size_t)NP * HD];   // mean writes -> p
__device__ float g_mp6[(size_t)NP * HD];   // mean rev_topic -> p
__device__ float g_ma2[(size_t)NA * HD];   // mean rev_writes -> a
__device__ float g_ma4[(size_t)NA * HD];   // mean rev_aff -> a
__device__ float g_mi3[(size_t)NI * HD];   // mean aff -> i
__device__ float g_mf5[(size_t)NF * HD];   // mean topic -> f

__device__ float g_pb[2][(size_t)NP * HD]; // ping-pong node features
__device__ float g_ab[2][(size_t)NA * HD];
__device__ float g_ib[2][(size_t)NI * HD];
__device__ float g_fb[2][(size_t)NF * HD];

__device__ float g_WrP[2 * HD * HD];       // combined Wr for paper (r0+r1+r6), per layer
__device__ float g_WrA[2 * HD * HD];       // combined Wr for author (r2+r4)
__device__ float g_bP[2 * HD];
__device__ float g_bA[2 * HD];

// CSR scratch: cnt doubles as cursor after scan
__device__ int g_cnt_c[NP];   __device__ int g_off_c[NP + 1];   __device__ int g_adj_c[E_C];
__device__ int g_cnt_w[NP];   __device__ int g_off_w[NP + 1];   __device__ int g_adj_w[E_W];
__device__ int g_cnt_rw[NA];  __device__ int g_off_rw[NA + 1];  __device__ int g_adj_rw[E_W];
__device__ int g_cnt_af[NI];  __device__ int g_off_af[NI + 1];  __device__ int g_adj_af[E_A];
__device__ int g_cnt_raf[NA]; __device__ int g_off_raf[NA + 1]; __device__ int g_adj_raf[E_A];
__device__ int g_cnt_t[NF];   __device__ int g_off_t[NF + 1];   __device__ int g_adj_t[E_T];
__device__ int g_cnt_rt[NP];  __device__ int g_off_rt[NP + 1];  __device__ int g_adj_rt[E_T];

// ---------------- small kernels ----------------
__global__ void hist_kernel(const int* __restrict__ dst, int E, int* cnt) {
    int i = blockIdx.x * blockDim.x + threadIdx.x;
    if (i < E) atomicAdd(&cnt[dst[i]], 1);
}

// single-block exclusive scan; writes offs[0..n] and overwrites cnt with cursor=offs
__global__ void scan_kernel(int* cnt, int n, int* offs) {
    __shared__ int sh[1024];
    int tid = threadIdx.x;
    int chunk = (n + 1023) >> 10;
    int beg = tid * chunk;
    int end = beg + chunk; if (end > n) end = n;
    int s = 0;
    for (int i = beg; i < end; i++) s += cnt[i];
    sh[tid] = s;
    __syncthreads();
    for (int d = 1; d < 1024; d <<= 1) {
        int t = (tid >= d) ? sh[tid - d] : 0;
        __syncthreads();
        sh[tid] += t;
        __syncthreads();
    }
    int run = sh[tid] - s;  // exclusive base
    for (int i = beg; i < end; i++) {
        int c = cnt[i];
        offs[i] = run;
        cnt[i]  = run;   // cursor init
        run += c;
    }
    if (beg < n && end == n) offs[n] = run;
}

__global__ void fill_kernel(const int* __restrict__ src, const int* __restrict__ dst,
                            int E, int* cursor, int* __restrict__ adj) {
    int i = blockIdx.x * blockDim.x + threadIdx.x;
    if (i < E) {
        int p = atomicAdd(&cursor[dst[i]], 1);
        adj[p] = src[i];
    }
}

// mean aggregation: 64 threads per dst node (float4 per thread), 4 nodes per block
__global__ void gather_mean_kernel(const float* __restrict__ x,
                                   const int* __restrict__ offs,
                                   const int* __restrict__ adj,
                                   float* __restrict__ out, int n_dst) {
    int node = blockIdx.x * 4 + (threadIdx.x >> 6);
    int lane = threadIdx.x & 63;
    if (node >= n_dst) return;
    int beg = offs[node], end = offs[node + 1];
    float4 acc = make_float4(0.f, 0.f, 0.f, 0.f);
    int e = beg;
    for (; e + 1 < end; e += 2) {
        int s0 = adj[e], s1 = adj[e + 1];
        float4 v0 = ((const float4*)(x + (size_t)s0 * HD))[lane];
        float4 v1 = ((const float4*)(x + (size_t)s1 * HD))[lane];
        acc.x += v0.x + v1.x; acc.y += v0.y + v1.y;
        acc.z += v0.z + v1.z; acc.w += v0.w + v1.w;
    }
    if (e < end) {
        float4 v = ((const float4*)(x + (size_t)adj[e] * HD))[lane];
        acc.x += v.x; acc.y += v.y; acc.z += v.z; acc.w += v.w;
    }
    float inv = (end > beg) ? 1.f / (float)(end - beg) : 0.f;
    float4 r = make_float4(acc.x * inv, acc.y * inv, acc.z * inv, acc.w * inv);
    ((float4*)(out + (size_t)node * HD))[lane] = r;
}

// combine per-relation Wr/bias into per-nodetype sums (linearity of x_dst @ Wr terms)
__global__ void combine_kernel(const float* __restrict__ Wr, const float* __restrict__ bl,
                               float* __restrict__ WrP, float* __restrict__ WrA,
                               float* __restrict__ bP, float* __restrict__ bA) {
    int idx = blockIdx.x * blockDim.x + threadIdx.x;
    if (idx < 2 * HD * HD) {
        int l = idx / (HD * HD), j = idx % (HD * HD);
        const float* base = Wr + (size_t)l * 7 * HD * HD;
        WrP[idx] = base[0 * HD * HD + j] + base[1 * HD * HD + j] + base[6 * HD * HD + j];
        WrA[idx] = base[2 * HD * HD + j] + base[4 * HD * HD + j];
    }
    if (idx < 2 * HD) {
        int l = idx / HD, j = idx % HD;
        const float* bb = bl + (size_t)l * 7 * HD;
        bP[idx] = bb[0 * HD + j] + bb[1 * HD + j] + bb[6 * HD + j];
        bA[idx] = bb[2 * HD + j] + bb[4 * HD + j];
    }
}

// ---------------- tf32 tensor-core multi-part GEMM ----------------
// C[M,N] = act( sum_p A_p[M,256] @ W_p[256,N] + bias ), tf32 mma.sync, fp32 accum.
struct GemmArgs {
    const float* A[4];
    const float* W[4];
    int nparts, M, N;
    const float* bias;
    float* C;
    int relu;
};

__device__ __forceinline__ float to_tf32(float x) {
    uint32_t u;
    asm("cvt.rna.tf32.f32 %0, %1;" : "=r"(u) : "f"(x));
    return __uint_as_float(u);
}

__device__ __forceinline__ void mma_tf32(float* c, const uint32_t* a, const uint32_t* b) {
    asm volatile(
        "mma.sync.aligned.m16n8k8.row.col.f32.tf32.tf32.f32 "
        "{%0,%1,%2,%3}, {%4,%5,%6,%7}, {%8,%9}, {%0,%1,%2,%3};\n"
        : "+f"(c[0]), "+f"(c[1]), "+f"(c[2]), "+f"(c[3])
        : "r"(a[0]), "r"(a[1]), "r"(a[2]), "r"(a[3]), "r"(b[0]), "r"(b[1]));
}

#define BK 32
#define APITCH 136  // 136 % 32 == 8 -> fragment loads (bank = 8*tig + g) conflict-free

__global__ __launch_bounds__(256) void gemm_tf32_kernel(GemmArgs g) {
    __shared__ float As[BK][APITCH];  // k-major: As[k][m]
    __shared__ float Bs[BK][APITCH];  // k-major: Bs[k][n]

    int tid = threadIdx.x;
    int bm = blockIdx.y * 128;
    int bn = blockIdx.x * 128;
    int warp = tid >> 5, lane = tid & 31;
    int warp_m = warp >> 2;          // 0..1  -> 64 rows each
    int warp_n = warp & 3;           // 0..3  -> 32 cols each
    int gq = lane >> 2, tig = lane & 3;

    // A loader: thread covers row lm, k-halves of 16
    int lm = tid & 127;
    int lk = tid >> 7;               // 0/1 -> k base lk*16
    bool arow_ok = (bm + lm) < g.M;

    // B loader: thread covers 4 cols at nc, k rows kr, kr+8, kr+16, kr+24
    int nc = (tid & 31) * 4;
    int kr = tid >> 5;               // 0..7

    float acc[4][4][4];
#pragma unroll
    for (int i = 0; i < 4; i++)
#pragma unroll
        for (int j = 0; j < 4; j++)
#pragma unroll
            for (int q = 0; q < 4; q++) acc[i][j][q] = 0.f;

    for (int p = 0; p < g.nparts; p++) {
        const float* A = g.A[p];
        const float* W = g.W[p];
        for (int k0 = 0; k0 < HD; k0 += BK) {
            // ---- load A tile (transpose to k-major, cvt to tf32) ----
            const float* Arow = A + (size_t)(bm + lm) * HD + k0 + lk * 16;
#pragma unroll
            for (int i = 0; i < 4; i++) {
                float4 v = make_float4(0.f, 0.f, 0.f, 0.f);
                if (arow_ok) v = *(const float4*)(Arow + i * 4);
                int kk = lk * 16 + i * 4;
                As[kk + 0][lm] = to_tf32(v.x);
                As[kk + 1][lm] = to_tf32(v.y);
                As[kk + 2][lm] = to_tf32(v.z);
                As[kk + 3][lm] = to_tf32(v.w);
            }
            // ---- load B tile (k-major already; scalar loads: N=349 rows unaligned) ----
#pragma unroll
            for (int i = 0; i < 4; i++) {
                int krow = kr + i * 8;
                const float* Wp = W + (size_t)(k0 + krow) * g.N + bn + nc;
                float4 v;
                v.x = (bn + nc + 0 < g.N) ? Wp[0] : 0.f;
                v.y = (bn + nc + 1 < g.N) ? Wp[1] : 0.f;
                v.z = (bn + nc + 2 < g.N) ? Wp[2] : 0.f;
                v.w = (bn + nc + 3 < g.N) ? Wp[3] : 0.f;
                v.x = to_tf32(v.x); v.y = to_tf32(v.y);
                v.z = to_tf32(v.z); v.w = to_tf32(v.w);
                *(float4*)(&Bs[krow][nc]) = v;
            }
            __syncthreads();

            // ---- 4 k8-steps of m16n8k8 tf32 mma ----
#pragma unroll
            for (int ks = 0; ks < 4; ks++) {
                int kb = ks * 8;
                uint32_t afr[4][4];
#pragma unroll
                for (int i = 0; i < 4; i++) {
                    int mb = warp_m * 64 + i * 16;
                    afr[i][0] = __float_as_uint(As[kb + tig][mb + gq]);
                    afr[i][1] = __float_as_uint(As[kb + tig][mb + gq + 8]);
                    afr[i][2] = __float_as_uint(As[kb + tig + 4][mb + gq]);
                    afr[i][3] = __float_as_uint(As[kb + tig + 4][mb + gq + 8]);
                }
                uint32_t bfr[4][2];
#pragma unroll
                for (int j = 0; j < 4; j++) {
                    int nb = warp_n * 32 + j * 8;
                    bfr[j][0] = __float_as_uint(Bs[kb + tig][nb + gq]);
                    bfr[j][1] = __float_as_uint(Bs[kb + tig + 4][nb + gq]);
                }
#pragma unroll
                for (int i = 0; i < 4; i++)
#pragma unroll
                    for (int j = 0; j < 4; j++)
                        mma_tf32(acc[i][j], afr[i], bfr[j]);
            }
            __syncthreads();
        }
    }

    // ---- epilogue: bias + relu + guarded store ----
#pragma unroll
    for (int i = 0; i < 4; i++) {
        int r0 = bm + warp_m * 64 + i * 16 + gq;
        int r1 = r0 + 8;
#pragma unroll
        for (int j = 0; j < 4; j++) {
            int c0 = bn + warp_n * 32 + j * 8 + tig * 2;
            float bia0 = 0.f, bia1 = 0.f;
            if (g.bias) {
                if (c0 < g.N)     bia0 = g.bias[c0];
                if (c0 + 1 < g.N) bia1 = g.bias[c0 + 1];
            }
            float v00 = acc[i][j][0] + bia0, v01 = acc[i][j][1] + bia1;
            float v10 = acc[i][j][2] + bia0, v11 = acc[i][j][3] + bia1;
            if (g.relu) {
                v00 = v00 > 0.f ? v00 : 0.f; v01 = v01 > 0.f ? v01 : 0.f;
                v10 = v10 > 0.f ? v10 : 0.f; v11 = v11 > 0.f ? v11 : 0.f;
            }
            if (r0 < g.M) {
                if (c0 < g.N)     g.C[(size_t)r0 * g.N + c0]     = v00;
                if (c0 + 1 < g.N) g.C[(size_t)r0 * g.N + c0 + 1] = v01;
            }
            if (r1 < g.M) {
                if (c0 < g.N)     g.C[(size_t)r1 * g.N + c0]     = v10;
                if (c0 + 1 < g.N) g.C[(size_t)r1 * g.N + c0 + 1] = v11;
            }
        }
    }
}

// ---------------- host ----------------
static inline int cdiv(int a, int b) { return (a + b - 1) / b; }

static void launch_gemm(int M, int N, int nparts,
                        const float* A0, const float* W0,
                        const float* A1, const float* W1,
                        const float* A2, const float* W2,
                        const float* A3, const float* W3,
                        const float* bias, float* C, int relu) {
    GemmArgs g;
    g.A[0] = A0; g.A[1] = A1; g.A[2] = A2; g.A[3] = A3;
    g.W[0] = W0; g.W[1] = W1; g.W[2] = W2; g.W[3] = W3;
    g.nparts = nparts; g.M = M; g.N = N;
    g.bias = bias; g.C = C; g.relu = relu;
    dim3 grid(cdiv(N, 128), cdiv(M, 128));
    gemm_tf32_kernel<<<grid, 256>>>(g);
}

extern "C" void kernel_launch(void* const* d_in, const int* in_sizes, int n_in,
                              void* d_out, int out_size) {
    const float* xp = (const float*)d_in[0];
    const float* xa = (const float*)d_in[1];
    const float* xi = (const float*)d_in[2];
    const float* xf = (const float*)d_in[3];
    const int* cites_src = (const int*)d_in[4];
    const int* cites_dst = (const int*)d_in[5];
    const int* writes_src = (const int*)d_in[6];
    const int* writes_dst = (const int*)d_in[7];
    const int* rwrites_src = (const int*)d_in[8];
    const int* rwrites_dst = (const int*)d_in[9];
    const int* aff_src = (const int*)d_in[10];
    const int* aff_dst = (const int*)d_in[11];
    const int* raff_src = (const int*)d_in[12];
    const int* raff_dst = (const int*)d_in[13];
    const int* topic_src = (const int*)d_in[14];
    const int* topic_dst = (const int*)d_in[15];
    const int* rtopic_src = (const int*)d_in[16];
    const int* rtopic_dst = (const int*)d_in[17];
    const float* Wl = (const float*)d_in[18];
    const float* bl = (const float*)d_in[19];
    const float* Wr = (const float*)d_in[20];
    const float* Wout = (const float*)d_in[21];
    const float* bout = (const float*)d_in[22];

    float *mp0, *mp1, *mp6, *ma2, *ma4, *mi3, *mf5;
    float *pb, *ab, *ib, *fb, *WrP, *WrA, *bP, *bA;
    int *cnt_c, *off_c, *adj_c, *cnt_w, *off_w, *adj_w;
    int *cnt_rw, *off_rw, *adj_rw, *cnt_af, *off_af, *adj_af;
    int *cnt_raf, *off_raf, *adj_raf, *cnt_t, *off_t, *adj_t;
    int *cnt_rt, *off_rt, *adj_rt;
    cudaGetSymbolAddress((void**)&mp0, g_mp0);
    cudaGetSymbolAddress((void**)&mp1, g_mp1);
    cudaGetSymbolAddress((void**)&mp6, g_mp6);
    cudaGetSymbolAddress((void**)&ma2, g_ma2);
    cudaGetSymbolAddress((void**)&ma4, g_ma4);
    cudaGetSymbolAddress((void**)&mi3, g_mi3);
    cudaGetSymbolAddress((void**)&mf5, g_mf5);
    cudaGetSymbolAddress((void**)&pb, g_pb);
    cudaGetSymbolAddress((void**)&ab, g_ab);
    cudaGetSymbolAddress((void**)&ib, g_ib);
    cudaGetSymbolAddress((void**)&fb, g_fb);
    cudaGetSymbolAddress((void**)&WrP, g_WrP);
    cudaGetSymbolAddress((void**)&WrA, g_WrA);
    cudaGetSymbolAddress((void**)&bP, g_bP);
    cudaGetSymbolAddress((void**)&bA, g_bA);
    cudaGetSymbolAddress((void**)&cnt_c, g_cnt_c);
    cudaGetSymbolAddress((void**)&off_c, g_off_c);
    cudaGetSymbolAddress((void**)&adj_c, g_adj_c);
    cudaGetSymbolAddress((void**)&cnt_w, g_cnt_w);
    cudaGetSymbolAddress((void**)&off_w, g_off_w);
    cudaGetSymbolAddress((void**)&adj_w, g_adj_w);
    cudaGetSymbolAddress((void**)&cnt_rw, g_cnt_rw);
    cudaGetSymbolAddress((void**)&off_rw, g_off_rw);
    cudaGetSymbolAddress((void**)&adj_rw, g_adj_rw);
    cudaGetSymbolAddress((void**)&cnt_af, g_cnt_af);
    cudaGetSymbolAddress((void**)&off_af, g_off_af);
    cudaGetSymbolAddress((void**)&adj_af, g_adj_af);
    cudaGetSymbolAddress((void**)&cnt_raf, g_cnt_raf);
    cudaGetSymbolAddress((void**)&off_raf, g_off_raf);
    cudaGetSymbolAddress((void**)&adj_raf, g_adj_raf);
    cudaGetSymbolAddress((void**)&cnt_t, g_cnt_t);
    cudaGetSymbolAddress((void**)&off_t, g_off_t);
    cudaGetSymbolAddress((void**)&adj_t, g_adj_t);
    cudaGetSymbolAddress((void**)&cnt_rt, g_cnt_rt);
    cudaGetSymbolAddress((void**)&off_rt, g_off_rt);
    cudaGetSymbolAddress((void**)&adj_rt, g_adj_rt);

    float* pbuf[2] = { pb, pb + (size_t)NP * HD };
    float* abuf[2] = { ab, ab + (size_t)NA * HD };
    float* ibuf[2] = { ib, ib + (size_t)NI * HD };
    float* fbuf[2] = { fb, fb + (size_t)NF * HD };

    // ---- build CSR for all 7 relations (reused by both layers) ----
    struct Rel { const int* src; const int* dst; int E; int n_dst; int* cnt; int* off; int* adj; };
    Rel rels[7] = {
        { cites_src,   cites_dst,   E_C, NP, cnt_c,   off_c,   adj_c   },
        { writes_src,  writes_dst,  E_W, NP, cnt_w,   off_w,   adj_w   },
        { rwrites_src, rwrites_dst, E_W, NA, cnt_rw,  off_rw,  adj_rw  },
        { aff_src,     aff_dst,     E_A, NI, cnt_af,  off_af,  adj_af  },
        { raff_src,    raff_dst,    E_A, NA, cnt_raf, off_raf, adj_raf },
        { topic_src,   topic_dst,   E_T, NF, cnt_t,   off_t,   adj_t   },
        { rtopic_src,  rtopic_dst,  E_T, NP, cnt_rt,  off_rt,  adj_rt  },
    };
    for (int r = 0; r < 7; r++) {
        cudaMemsetAsync(rels[r].cnt, 0, (size_t)rels[r].n_dst * sizeof(int), 0);
        hist_kernel<<<cdiv(rels[r].E, 256), 256>>>(rels[r].dst, rels[r].E, rels[r].cnt);
        scan_kernel<<<1, 1024>>>(rels[r].cnt, rels[r].n_dst, rels[r].off);
        fill_kernel<<<cdiv(rels[r].E, 256), 256>>>(rels[r].src, rels[r].dst, rels[r].E,
                                                   rels[r].cnt, rels[r].adj);
    }

    // ---- combine Wr / biases per node type (both layers) ----
    combine_kernel<<<cdiv(2 * HD * HD, 256), 256>>>(Wr, bl, WrP, WrA, bP, bA);

    // ---- 2 SAGE layers ----
    const float* cp = xp; const float* ca = xa; const float* ci = xi; const float* cf = xf;
    for (int l = 0; l < 2; l++) {
        gather_mean_kernel<<<cdiv(NP, 4), 256>>>(cp, off_c,   adj_c,   mp0, NP);
        gather_mean_kernel<<<cdiv(NP, 4), 256>>>(ca, off_w,   adj_w,   mp1, NP);
        gather_mean_kernel<<<cdiv(NP, 4), 256>>>(cf, off_rt,  adj_rt,  mp6, NP);
        gather_mean_kernel<<<cdiv(NA, 4), 256>>>(cp, off_rw,  adj_rw,  ma2, NA);
        gather_mean_kernel<<<cdiv(NA, 4), 256>>>(ci, off_raf, adj_raf, ma4, NA);
        gather_mean_kernel<<<cdiv(NI, 4), 256>>>(ca, off_af,  adj_af,  mi3, NI);
        gather_mean_kernel<<<cdiv(NF, 4), 256>>>(cp, off_t,   adj_t,   mf5, NF);

        const size_t WSZ = (size_t)HD * HD;
        const float* WlL = Wl + (size_t)l * 7 * WSZ;
        const float* blL = bl + (size_t)l * 7 * HD;

        // new_p = relu(mp0@Wl0 + mp1@Wl1 + mp6@Wl6 + p@(Wr0+Wr1+Wr6) + (bl0+bl1+bl6))
        launch_gemm(NP, HD, 4,
                    mp0, WlL + 0 * WSZ, mp1, WlL + 1 * WSZ,
                    mp6, WlL + 6 * WSZ, cp, WrP + (size_t)l * WSZ,
                    bP + (size_t)l * HD, pbuf[l], 1);
        // new_a
        launch_gemm(NA, HD, 3,
                    ma2, WlL + 2 * WSZ, ma4, WlL + 4 * WSZ,
                    ca, WrA + (size_t)l * WSZ, 0, 0,
                    bA + (size_t)l * HD, abuf[l], 1);
        // new_i
        launch_gemm(NI, HD, 2,
                    mi3, WlL + 3 * WSZ, ci, Wr + ((size_t)l * 7 + 3) * WSZ,
                    0, 0, 0, 0,
                    blL + 3 * HD, ibuf[l], 1);
        // new_f
        launch_gemm(NF, HD, 2,
                    mf5, WlL + 5 * WSZ, cf, Wr + ((size_t)l * 7 + 5) * WSZ,
                    0, 0, 0, 0,
                    blL + 5 * HD, fbuf[l], 1);

        cp = pbuf[l]; ca = abuf[l]; ci = ibuf[l]; cf = fbuf[l];
    }

    // ---- final projection: out = p @ W_out + b_out ----
    launch_gemm(NP, NOUT, 1, cp, Wout, 0, 0, 0, 0, 0, 0,
                bout, (float*)d_out, 0);
}